// round 16
// baseline (speedup 1.0000x reference)
#include <cuda_runtime.h>
#include <cuda_fp16.h>
#include <cstdint>

// Problem constants
#define BB   16
#define NN   2048
#define TT   168
#define DD   64
#define MM   2216            // N + T
#define PADM 2304            // padded rows, zero-filled
#define TMR  64              // tile rows (A strip)
#define TNC  128             // tile cols (B strip)
#define NTJ  18
#define TILES_PER_B 341      // per batch, j >= floor(i/2)
#define TOTAL_TILES (TILES_PER_B * BB)   // 5456
#define NCTA 608             // 152 SMs * 4 -> one exact wave

// SMEM: A hi 8KB + A lo 8KB resident at [0,16K); B hi 16KB at [16K,32K).
// After MMA, Cs float[c:128][r: pitch 68] = 34816B overlays [16K, 51200).
#define AHI_OFF 0
#define ALO_OFF 8192
#define BHI_OFF 16384
#define CS_OFF  16384
#define CS_PITCH 68
#define SMEM_BYTES 51200     // 16384 + 34816; 4 CTAs/SM (204.8KB)

// global hi/lo scratch: [BB][PADM][DD] fp16
__device__ __half g_hi[(size_t)BB * PADM * DD];
__device__ __half g_lo[(size_t)BB * PADM * DD];

__device__ __forceinline__ uint32_t smem_u32(const void* p) {
    uint32_t a;
    asm("{ .reg .u64 t; cvta.to.shared.u64 t, %1; cvt.u32.u64 %0, t; }" : "=r"(a) : "l"(p));
    return a;
}

__device__ __forceinline__ float tanh_relu(float x) {
    x = fmaxf(x, 0.0f);
    float y;
    asm("tanh.approx.f32 %0, %1;" : "=f"(y) : "f"(x));
    return y;
}

__device__ __forceinline__ uint32_t sw128(uint32_t off) {
    return off ^ ((off >> 3) & 0x70);
}

// streaming stores (evict-first): output is write-once
__device__ __forceinline__ void stcs_f2(float* p, float x, float y) {
    asm volatile("st.global.cs.v2.f32 [%0], {%1, %2};" :: "l"(p), "f"(x), "f"(y) : "memory");
}
__device__ __forceinline__ void stcs_f4(float* p, float4 v) {
    asm volatile("st.global.cs.v4.f32 [%0], {%1, %2, %3, %4};"
                 :: "l"(p), "f"(v.x), "f"(v.y), "f"(v.z), "f"(v.w) : "memory");
}
__device__ __forceinline__ void stcs_f1(float* p, float x) {
    asm volatile("st.global.cs.f32 [%0], %1;" :: "l"(p), "f"(x) : "memory");
}

__device__ __forceinline__ void cpasync16(uint32_t dst, const void* src) {
    asm volatile("cp.async.cg.shared.global [%0], [%1], 16;" :: "r"(dst), "l"(src) : "memory");
}
__device__ __forceinline__ void cpasync_wait_all() {
    asm volatile("cp.async.commit_group;\n\tcp.async.wait_group 0;" ::: "memory");
}

// convert 8 floats -> 16B hi + 16B lo fp16 packs
__device__ __forceinline__ void split8h(float4 v0, float4 v1, uint4& hp, uint4& lp) {
    __half2 h01 = __floats2half2_rn(v0.x, v0.y);
    __half2 h23 = __floats2half2_rn(v0.z, v0.w);
    __half2 h45 = __floats2half2_rn(v1.x, v1.y);
    __half2 h67 = __floats2half2_rn(v1.z, v1.w);
    __half2 l01 = __floats2half2_rn(
        v0.x - __half2float(__low2half(h01)),
        v0.y - __half2float(__high2half(h01)));
    __half2 l23 = __floats2half2_rn(
        v0.z - __half2float(__low2half(h23)),
        v0.w - __half2float(__high2half(h23)));
    __half2 l45 = __floats2half2_rn(
        v1.x - __half2float(__low2half(h45)),
        v1.y - __half2float(__high2half(h45)));
    __half2 l67 = __floats2half2_rn(
        v1.z - __half2float(__low2half(h67)),
        v1.w - __half2float(__high2half(h67)));
    hp.x = *(uint32_t*)&h01; hp.y = *(uint32_t*)&h23;
    hp.z = *(uint32_t*)&h45; hp.w = *(uint32_t*)&h67;
    lp.x = *(uint32_t*)&l01; lp.y = *(uint32_t*)&l23;
    lp.z = *(uint32_t*)&l45; lp.w = *(uint32_t*)&l67;
}

// ---- prep: decompose all inputs into g_hi/g_lo (zero-padded rows) ----
__global__ __launch_bounds__(256)
void prep_kernel(const float* __restrict__ sp, const float* __restrict__ tp)
{
    int chunk = blockIdx.x * 256 + threadIdx.x;
    const int total = BB * PADM * (DD / 8);
    if (chunk >= total) return;
    int e0  = chunk * 8;
    int b   = e0 / (PADM * DD);
    int rem = e0 - b * PADM * DD;
    int g   = rem / DD;
    int k   = rem - g * DD;
    uint4 hp = make_uint4(0,0,0,0), lp = make_uint4(0,0,0,0);
    if (g < MM) {
        const float* ptr = (g < NN) ? sp + ((size_t)b * NN + g) * DD
                                    : tp + ((size_t)b * TT + (g - NN)) * DD;
        float4 v0 = *(const float4*)(ptr + k);
        float4 v1 = *(const float4*)(ptr + k + 4);
        split8h(v0, v1, hp, lp);
    }
    ((uint4*)g_hi)[chunk] = hp;
    ((uint4*)g_lo)[chunk] = lp;
}

__device__ __forceinline__ void ldsm_x4(uint32_t addr, uint32_t& r0, uint32_t& r1,
                                        uint32_t& r2, uint32_t& r3) {
    asm volatile("ldmatrix.sync.aligned.m8n8.x4.shared.b16 {%0,%1,%2,%3}, [%4];"
                 : "=r"(r0), "=r"(r1), "=r"(r2), "=r"(r3) : "r"(addr));
}

__device__ __forceinline__ void mma16816h(float* c, const uint32_t* a, const uint32_t* b) {
    asm volatile(
        "mma.sync.aligned.m16n8k16.row.col.f32.f16.f16.f32 "
        "{%0,%1,%2,%3}, {%4,%5,%6,%7}, {%8,%9}, {%0,%1,%2,%3};"
        : "+f"(c[0]), "+f"(c[1]), "+f"(c[2]), "+f"(c[3])
        : "r"(a[0]), "r"(a[1]), "r"(a[2]), "r"(a[3]), "r"(b[0]), "r"(b[1]));
}

// within-batch tile decode: same (m-pair, j) ordering as R15 -> consecutive
// p share i in runs of (18 - m) tiles
__device__ __forceinline__ void decode_ij(int p, int& i, int& j) {
    int m = 0;
    while (m < 17 && p >= 2 * (NTJ - m)) { p -= 2 * (NTJ - m); ++m; }
    if (m == 17) { i = 34; j = 17; }
    else {
        int cnt = NTJ - m;
        if (p >= cnt) { i = 2 * m + 1; j = m + (p - cnt); }
        else          { i = 2 * m;     j = m + p; }
    }
}

__global__ __launch_bounds__(128, 4)
void stg_sym9_kernel(float* __restrict__ out)
{
    extern __shared__ char smem[];
    const uint32_t smem_base = smem_u32(smem);

    const int t    = threadIdx.x;
    const int lane = t & 31;
    const int wid  = t >> 5;

    // chunk assignment: 592 CTAs x 9 + 16 CTAs x 8 = 5456 tiles
    const int id = blockIdx.x;
    int start, cnt;
    if (id < 592) { start = id * 9; cnt = 9; }
    else          { start = 5328 + (id - 592) * 8; cnt = 8; }

    const int m0w = (wid & 1) * 32;
    const int n0w = (wid >> 1) * 64;
    const int a_row  = m0w + (lane & 15);
    const int a_chk  = lane >> 4;
    const int b_rowb = n0w + ((lane >> 4) << 3) + (lane & 7);
    const int b_chk  = (lane >> 3) & 1;

    const uint32_t ahibase = smem_base + AHI_OFF;
    const uint32_t alobase = smem_base + ALO_OFF;
    const uint32_t bhibase = smem_base + BHI_OFF;

    int cur_bi = -1;

    for (int tt = start; tt < start + cnt; ++tt) {
        // ---- decode tile (b, i, j) ----
        const int b = tt / TILES_PER_B;
        int i, j;
        decode_ij(tt - b * TILES_PER_B, i, j);
        const int row0 = i * TMR;
        const int col0 = j * TNC;
        const int abi  = b * 35 + i;
        const bool a_new = (abi != cur_bi);
        cur_bi = abi;

        // ---- async loads: A only on strip change (resident), B every tile ----
        const char* hib = (const char*)g_hi + (size_t)b * PADM * 128;
        const char* lob = (const char*)g_lo + (size_t)b * PADM * 128;
        if (a_new) {
            #pragma unroll
            for (int it = 0; it < 4; ++it) {
                int idx = it * 128 + t;
                int r   = idx >> 3;
                int c8  = idx & 7;
                size_t go  = (size_t)(row0 + r) * 128 + c8 * 16;
                uint32_t sw = sw128((uint32_t)r * 128 + (uint32_t)c8 * 16);
                cpasync16(ahibase + sw, hib + go);
                cpasync16(alobase + sw, lob + go);
            }
        }
        #pragma unroll
        for (int it = 0; it < 8; ++it) {
            int idx = it * 128 + t;
            int r   = idx >> 3;
            int c8  = idx & 7;
            size_t go  = (size_t)(col0 + r) * 128 + c8 * 16;
            uint32_t sw = sw128((uint32_t)r * 128 + (uint32_t)c8 * 16);
            cpasync16(bhibase + sw, hib + go);
        }
        cpasync_wait_all();
        __syncthreads();

        // ---- MMA: kc-outer, 2-pass fp16 split ----
        float acc[2][8][4];
        #pragma unroll
        for (int mi = 0; mi < 2; ++mi)
            #pragma unroll
            for (int ni = 0; ni < 8; ++ni)
                #pragma unroll
                for (int q = 0; q < 4; ++q) acc[mi][ni][q] = 0.0f;

        #pragma unroll
        for (int kk = 0; kk < 4; ++kk) {
            const int kc = kk * 2;
            uint32_t a_off[2], b_off[4];
            #pragma unroll
            for (int mi = 0; mi < 2; ++mi)
                a_off[mi] = sw128((uint32_t)(a_row + mi * 16) * 128 + (uint32_t)(kc + a_chk) * 16);
            #pragma unroll
            for (int bi = 0; bi < 4; ++bi)
                b_off[bi] = sw128((uint32_t)(b_rowb + bi * 16) * 128 + (uint32_t)(kc + b_chk) * 16);

            uint32_t af[2][4], bfh[8][2];
            #pragma unroll
            for (int bi = 0; bi < 4; ++bi)
                ldsm_x4(bhibase + b_off[bi], bfh[2*bi][0], bfh[2*bi][1], bfh[2*bi+1][0], bfh[2*bi+1][1]);
            #pragma unroll
            for (int mi = 0; mi < 2; ++mi)
                ldsm_x4(ahibase + a_off[mi], af[mi][0], af[mi][1], af[mi][2], af[mi][3]);
            #pragma unroll
            for (int mi = 0; mi < 2; ++mi)
                #pragma unroll
                for (int ni = 0; ni < 8; ++ni)
                    mma16816h(acc[mi][ni], af[mi], bfh[ni]);     // Ah*Bh
            #pragma unroll
            for (int mi = 0; mi < 2; ++mi)
                ldsm_x4(alobase + a_off[mi], af[mi][0], af[mi][1], af[mi][2], af[mi][3]);
            #pragma unroll
            for (int mi = 0; mi < 2; ++mi)
                #pragma unroll
                for (int ni = 0; ni < 8; ++ni)
                    mma16816h(acc[mi][ni], af[mi], bfh[ni]);     // Al*Bh
        }

        // ---- activation ----
        #pragma unroll
        for (int mi = 0; mi < 2; ++mi)
            #pragma unroll
            for (int ni = 0; ni < 8; ++ni)
                #pragma unroll
                for (int q = 0; q < 4; ++q)
                    acc[mi][ni][q] = tanh_relu(acc[mi][ni][q]);

        // ---- direct write: coalesced streaming float2 ----
        #pragma unroll
        for (int mi = 0; mi < 2; ++mi) {
            #pragma unroll
            for (int rh = 0; rh < 2; ++rh) {
                const int gr = row0 + m0w + mi * 16 + rh * 8 + (lane >> 2);
                if (gr >= MM) continue;
                const size_t rbase = ((size_t)b * MM + gr) * MM;
                #pragma unroll
                for (int ni = 0; ni < 8; ++ni) {
                    const int gc = col0 + n0w + ni * 8 + (lane & 3) * 2;
                    if (gc < MM)
                        stcs_f2(&out[rbase + gc], acc[mi][ni][rh * 2], acc[mi][ni][rh * 2 + 1]);
                }
            }
        }

        // ---- mirror via Cs overlay on B region (A untouched) ----
        __syncthreads();               // MMA reads of A & B done
        {
            float* Cs = (float*)(smem + CS_OFF);   // [c:128][r: pitch 68]
            #pragma unroll
            for (int mi = 0; mi < 2; ++mi) {
                #pragma unroll
                for (int rh = 0; rh < 2; ++rh) {
                    const int r = m0w + mi * 16 + rh * 8 + (lane >> 2);
                    #pragma unroll
                    for (int ni = 0; ni < 8; ++ni) {
                        const int c = n0w + ni * 8 + (lane & 3) * 2;
                        Cs[(c)     * CS_PITCH + r] = acc[mi][ni][rh * 2];
                        Cs[(c + 1) * CS_PITCH + r] = acc[mi][ni][rh * 2 + 1];
                    }
                }
            }
            __syncthreads();
            #pragma unroll
            for (int it = 0; it < 16; ++it) {
                int u   = it * 128 + t;
                int lr4 = u & 15;
                int lc  = u >> 4;
                float4 v = *(const float4*)&Cs[lc * CS_PITCH + 4 * lr4];
                int gr_out = col0 + lc;
                int gc_out = row0 + 4 * lr4;
                if (gr_out < MM && gc_out + 3 < MM) {
                    stcs_f4(&out[((size_t)b * MM + gr_out) * MM + gc_out], v);
                } else if (gr_out < MM) {
                    float* dst = &out[((size_t)b * MM + gr_out) * MM + gc_out];
                    if (gc_out     < MM) stcs_f1(dst + 0, v.x);
                    if (gc_out + 1 < MM) stcs_f1(dst + 1, v.y);
                    if (gc_out + 2 < MM) stcs_f1(dst + 2, v.z);
                    if (gc_out + 3 < MM) stcs_f1(dst + 3, v.w);
                }
            }
        }
        __syncthreads();               // Cs reads done before next B load clobbers region
    }
}

extern "C" void kernel_launch(void* const* d_in, const int* in_sizes, int n_in,
                              void* d_out, int out_size)
{
    const float* sp = (const float*)d_in[0];   // spatial  [16,2048,64] f32
    const float* tp = (const float*)d_in[1];   // temporal [16, 168,64] f32
    float* out = (float*)d_out;                // [16,2216,2216] f32

    // 1) decompose inputs into g_hi/g_lo (fp16, zero-padded)
    const int total_chunks = BB * PADM * (DD / 8);
    prep_kernel<<<(total_chunks + 255) / 256, 256>>>(sp, tp);

    // 2) persistent symmetric GEMM (2-pass fp16, resident A)
    cudaFuncSetAttribute(stg_sym9_kernel, cudaFuncAttributeMaxDynamicSharedMemorySize, SMEM_BYTES);
    stg_sym9_kernel<<<NCTA, 128, SMEM_BYTES>>>(out);
}

// round 17
// speedup vs baseline: 1.0307x; 1.0307x over previous
#include <cuda_runtime.h>
#include <cuda_fp16.h>
#include <cstdint>

// Problem constants
#define BB   16
#define NN   2048
#define TT   168
#define DD   64
#define MM   2216            // N + T
#define PADM 2304            // padded rows, zero-filled
#define TMR  64              // tile rows (A strip)
#define TNC  128             // tile cols (B strip)
#define NTJ  18
#define TILES_PER_B 341      // sum over i of (18 - floor(i/2))

// SMEM: fp16 tiles, 128B rows, SW128-swizzled. A hi 8KB + A lo 8KB + B hi 16KB = 32KB.
// After MMA, reused as Cs float[c:128][r: pitch 68] = 34816 B.
#define AHI_OFF 0
#define ALO_OFF 8192
#define BHI_OFF 16384
#define CS_PITCH 68
#define SMEM_BYTES 34816     // 4 CTAs/SM (reg-capped anyway)

// global hi/lo scratch: [BB][PADM][DD] fp16
__device__ __half g_hi[(size_t)BB * PADM * DD];
__device__ __half g_lo[(size_t)BB * PADM * DD];

__device__ __forceinline__ uint32_t smem_u32(const void* p) {
    uint32_t a;
    asm("{ .reg .u64 t; cvta.to.shared.u64 t, %1; cvt.u32.u64 %0, t; }" : "=r"(a) : "l"(p));
    return a;
}

__device__ __forceinline__ float tanh_relu(float x) {
    x = fmaxf(x, 0.0f);
    float y;
    asm("tanh.approx.f32 %0, %1;" : "=f"(y) : "f"(x));
    return y;
}

__device__ __forceinline__ uint32_t sw128(uint32_t off) {
    return off ^ ((off >> 3) & 0x70);
}

// streaming stores (evict-first): output is write-once
__device__ __forceinline__ void stcs_f2(float* p, float x, float y) {
    asm volatile("st.global.cs.v2.f32 [%0], {%1, %2};" :: "l"(p), "f"(x), "f"(y) : "memory");
}
__device__ __forceinline__ void stcs_f4(float* p, float4 v) {
    asm volatile("st.global.cs.v4.f32 [%0], {%1, %2, %3, %4};"
                 :: "l"(p), "f"(v.x), "f"(v.y), "f"(v.z), "f"(v.w) : "memory");
}
__device__ __forceinline__ void stcs_f1(float* p, float x) {
    asm volatile("st.global.cs.f32 [%0], %1;" :: "l"(p), "f"(x) : "memory");
}

__device__ __forceinline__ void cpasync16(uint32_t dst, const void* src) {
    asm volatile("cp.async.cg.shared.global [%0], [%1], 16;" :: "r"(dst), "l"(src) : "memory");
}
__device__ __forceinline__ void cpasync_wait_all() {
    asm volatile("cp.async.commit_group;\n\tcp.async.wait_group 0;" ::: "memory");
}

// convert 8 floats -> 16B hi + 16B lo fp16 packs
__device__ __forceinline__ void split8h(float4 v0, float4 v1, uint4& hp, uint4& lp) {
    __half2 h01 = __floats2half2_rn(v0.x, v0.y);
    __half2 h23 = __floats2half2_rn(v0.z, v0.w);
    __half2 h45 = __floats2half2_rn(v1.x, v1.y);
    __half2 h67 = __floats2half2_rn(v1.z, v1.w);
    __half2 l01 = __floats2half2_rn(
        v0.x - __half2float(__low2half(h01)),
        v0.y - __half2float(__high2half(h01)));
    __half2 l23 = __floats2half2_rn(
        v0.z - __half2float(__low2half(h23)),
        v0.w - __half2float(__high2half(h23)));
    __half2 l45 = __floats2half2_rn(
        v1.x - __half2float(__low2half(h45)),
        v1.y - __half2float(__high2half(h45)));
    __half2 l67 = __floats2half2_rn(
        v1.z - __half2float(__low2half(h67)),
        v1.w - __half2float(__high2half(h67)));
    hp.x = *(uint32_t*)&h01; hp.y = *(uint32_t*)&h23;
    hp.z = *(uint32_t*)&h45; hp.w = *(uint32_t*)&h67;
    lp.x = *(uint32_t*)&l01; lp.y = *(uint32_t*)&l23;
    lp.z = *(uint32_t*)&l45; lp.w = *(uint32_t*)&l67;
}

// ---- prep: decompose all inputs into g_hi/g_lo (zero-padded rows) ----
__global__ __launch_bounds__(256)
void prep_kernel(const float* __restrict__ sp, const float* __restrict__ tp)
{
    int chunk = blockIdx.x * 256 + threadIdx.x;
    const int total = BB * PADM * (DD / 8);
    if (chunk >= total) return;
    int e0  = chunk * 8;
    int b   = e0 / (PADM * DD);
    int rem = e0 - b * PADM * DD;
    int g   = rem / DD;
    int k   = rem - g * DD;
    uint4 hp = make_uint4(0,0,0,0), lp = make_uint4(0,0,0,0);
    if (g < MM) {
        const float* ptr = (g < NN) ? sp + ((size_t)b * NN + g) * DD
                                    : tp + ((size_t)b * TT + (g - NN)) * DD;
        float4 v0 = *(const float4*)(ptr + k);
        float4 v1 = *(const float4*)(ptr + k + 4);
        split8h(v0, v1, hp, lp);
    }
    ((uint4*)g_hi)[chunk] = hp;
    ((uint4*)g_lo)[chunk] = lp;
}

__device__ __forceinline__ void ldsm_x4(uint32_t addr, uint32_t& r0, uint32_t& r1,
                                        uint32_t& r2, uint32_t& r3) {
    asm volatile("ldmatrix.sync.aligned.m8n8.x4.shared.b16 {%0,%1,%2,%3}, [%4];"
                 : "=r"(r0), "=r"(r1), "=r"(r2), "=r"(r3) : "r"(addr));
}

__device__ __forceinline__ void mma16816h(float* c, const uint32_t* a, const uint32_t* b) {
    asm volatile(
        "mma.sync.aligned.m16n8k16.row.col.f32.f16.f16.f32 "
        "{%0,%1,%2,%3}, {%4,%5,%6,%7}, {%8,%9}, {%0,%1,%2,%3};"
        : "+f"(c[0]), "+f"(c[1]), "+f"(c[2]), "+f"(c[3])
        : "r"(a[0]), "r"(a[1]), "r"(a[2]), "r"(a[3]), "r"(b[0]), "r"(b[1]));
}

__global__ __launch_bounds__(128, 4)
void stg_sym10_kernel(float* __restrict__ out)
{
    extern __shared__ char smem[];
    const uint32_t smem_base = smem_u32(smem);

    const int t    = threadIdx.x;
    const int lane = t & 31;
    const int wid  = t >> 5;

    const int b = blockIdx.y;

    // map blockIdx.x -> (i strip of 64 rows, j strip of 128 cols), j >= floor(i/2)
    int p = blockIdx.x;
    int m = 0;
    while (m < 17 && p >= 2 * (NTJ - m)) { p -= 2 * (NTJ - m); ++m; }
    int i, j;
    if (m == 17) { i = 34; j = 17; }
    else {
        int cnt = NTJ - m;
        if (p >= cnt) { i = 2 * m + 1; j = m + (p - cnt); }
        else          { i = 2 * m;     j = m + p; }
    }
    const int row0 = i * TMR;
    const int col0 = j * TNC;
    const bool crossing = (j == (i >> 1));   // tile straddles the diagonal

    // ---- async tile loads from pre-decomposed hi/lo (branch-free, swizzled) ----
    const char* hib = (const char*)g_hi + (size_t)b * PADM * 128;   // 128B per row
    const char* lob = (const char*)g_lo + (size_t)b * PADM * 128;
    {
        // B first (larger): 128 rows * 8 chunks = 1024 -> 8 iters (hi only)
        #pragma unroll
        for (int it = 0; it < 8; ++it) {
            int idx = it * 128 + t;
            int r   = idx >> 3;
            int c8  = idx & 7;
            size_t go  = (size_t)(col0 + r) * 128 + c8 * 16;
            uint32_t sw = sw128((uint32_t)r * 128 + (uint32_t)c8 * 16);
            cpasync16(smem_base + BHI_OFF + sw, hib + go);
        }
        // A: 64 rows * 8 chunks = 512 / 128 thr = 4 iters (hi + lo)
        #pragma unroll
        for (int it = 0; it < 4; ++it) {
            int idx = it * 128 + t;
            int r   = idx >> 3;
            int c8  = idx & 7;
            size_t go  = (size_t)(row0 + r) * 128 + c8 * 16;
            uint32_t sw = sw128((uint32_t)r * 128 + (uint32_t)c8 * 16);
            cpasync16(smem_base + AHI_OFF + sw, hib + go);
            cpasync16(smem_base + ALO_OFF + sw, lob + go);
        }
        cpasync_wait_all();
    }
    __syncthreads();

    // ---- warp tiles: 2 (m) x 2 (n) warps, each 32x64 ----
    const int m0w = (wid & 1) * 32;
    const int n0w = (wid >> 1) * 64;

    float acc[2][8][4];
    #pragma unroll
    for (int mi = 0; mi < 2; ++mi)
        #pragma unroll
        for (int ni = 0; ni < 8; ++ni)
            #pragma unroll
            for (int q = 0; q < 4; ++q) acc[mi][ni][q] = 0.0f;

    const int a_row  = m0w + (lane & 15);
    const int a_chk  = lane >> 4;
    const int b_rowb = n0w + ((lane >> 4) << 3) + (lane & 7);
    const int b_chk  = (lane >> 3) & 1;

    const uint32_t ahibase = smem_base + AHI_OFF;
    const uint32_t alobase = smem_base + ALO_OFF;
    const uint32_t bhibase = smem_base + BHI_OFF;

    // kc-outer: per k-chunk load each fragment set once, run both passes
    #pragma unroll
    for (int kk = 0; kk < 4; ++kk) {
        const int kc = kk * 2;
        uint32_t a_off[2], b_off[4];
        #pragma unroll
        for (int mi = 0; mi < 2; ++mi)
            a_off[mi] = sw128((uint32_t)(a_row + mi * 16) * 128 + (uint32_t)(kc + a_chk) * 16);
        #pragma unroll
        for (int bi = 0; bi < 4; ++bi)
            b_off[bi] = sw128((uint32_t)(b_rowb + bi * 16) * 128 + (uint32_t)(kc + b_chk) * 16);

        uint32_t af[2][4], bfh[8][2];
        #pragma unroll
        for (int bi = 0; bi < 4; ++bi)
            ldsm_x4(bhibase + b_off[bi], bfh[2*bi][0], bfh[2*bi][1], bfh[2*bi+1][0], bfh[2*bi+1][1]);
        #pragma unroll
        for (int mi = 0; mi < 2; ++mi)
            ldsm_x4(ahibase + a_off[mi], af[mi][0], af[mi][1], af[mi][2], af[mi][3]);
        #pragma unroll
        for (int mi = 0; mi < 2; ++mi)
            #pragma unroll
            for (int ni = 0; ni < 8; ++ni)
                mma16816h(acc[mi][ni], af[mi], bfh[ni]);         // Ah*Bh
        #pragma unroll
        for (int mi = 0; mi < 2; ++mi)
            ldsm_x4(alobase + a_off[mi], af[mi][0], af[mi][1], af[mi][2], af[mi][3]);
        #pragma unroll
        for (int mi = 0; mi < 2; ++mi)
            #pragma unroll
            for (int ni = 0; ni < 8; ++ni)
                mma16816h(acc[mi][ni], af[mi], bfh[ni]);         // Al*Bh
    }

    // ---- activation in place (f32 MUFU) ----
    #pragma unroll
    for (int mi = 0; mi < 2; ++mi)
        #pragma unroll
        for (int ni = 0; ni < 8; ++ni)
            #pragma unroll
            for (int q = 0; q < 4; ++q)
                acc[mi][ni][q] = tanh_relu(acc[mi][ni][q]);

    // ---- direct write: out[row0+r][col0+c], coalesced streaming float2 ----
    // crossing tiles: skip strictly-below-diagonal pairs (covered by mirrors elsewhere)
    #pragma unroll
    for (int mi = 0; mi < 2; ++mi) {
        #pragma unroll
        for (int rh = 0; rh < 2; ++rh) {
            const int gr = row0 + m0w + mi * 16 + rh * 8 + (lane >> 2);
            if (gr >= MM) continue;
            const size_t rbase = ((size_t)b * MM + gr) * MM;
            #pragma unroll
            for (int ni = 0; ni < 8; ++ni) {
                const int gc = col0 + n0w + ni * 8 + (lane & 3) * 2;
                if (gc < MM && (!crossing || gr <= gc + 1))
                    stcs_f2(&out[rbase + gc], acc[mi][ni][rh * 2], acc[mi][ni][rh * 2 + 1]);
            }
        }
    }

    // ---- mirror write via SMEM transpose ----
    // crossing tiles: skip strictly-above-diagonal f4s (covered by direct passes)
    __syncthreads();                   // done reading A/B tiles
    {
        float* Cs = (float*)smem;      // [c:128][r: pitch 68]
        #pragma unroll
        for (int mi = 0; mi < 2; ++mi) {
            #pragma unroll
            for (int rh = 0; rh < 2; ++rh) {
                const int r = m0w + mi * 16 + rh * 8 + (lane >> 2);
                #pragma unroll
                for (int ni = 0; ni < 8; ++ni) {
                    const int c = n0w + ni * 8 + (lane & 3) * 2;
                    Cs[(c)     * CS_PITCH + r] = acc[mi][ni][rh * 2];
                    Cs[(c + 1) * CS_PITCH + r] = acc[mi][ni][rh * 2 + 1];
                }
            }
        }
        __syncthreads();
        #pragma unroll
        for (int it = 0; it < 16; ++it) {
            int u   = it * 128 + t;
            int lr4 = u & 15;
            int lc  = u >> 4;
            int gr_out = col0 + lc;
            int gc_out = row0 + 4 * lr4;
            if (crossing && gc_out > gr_out) continue;   // entire f4 above diagonal
            float4 v = *(const float4*)&Cs[lc * CS_PITCH + 4 * lr4];
            if (gr_out < MM && gc_out + 3 < MM) {
                stcs_f4(&out[((size_t)b * MM + gr_out) * MM + gc_out], v);
            } else if (gr_out < MM) {
                float* dst = &out[((size_t)b * MM + gr_out) * MM + gc_out];
                if (gc_out     < MM) stcs_f1(dst + 0, v.x);
                if (gc_out + 1 < MM) stcs_f1(dst + 1, v.y);
                if (gc_out + 2 < MM) stcs_f1(dst + 2, v.z);
                if (gc_out + 3 < MM) stcs_f1(dst + 3, v.w);
            }
        }
    }
}

extern "C" void kernel_launch(void* const* d_in, const int* in_sizes, int n_in,
                              void* d_out, int out_size)
{
    const float* sp = (const float*)d_in[0];   // spatial  [16,2048,64] f32
    const float* tp = (const float*)d_in[1];   // temporal [16, 168,64] f32
    float* out = (float*)d_out;                // [16,2216,2216] f32

    // 1) decompose inputs into g_hi/g_lo (fp16, zero-padded)
    const int total_chunks = BB * PADM * (DD / 8);
    prep_kernel<<<(total_chunks + 255) / 256, 256>>>(sp, tp);

    // 2) main symmetric GEMM (2-pass fp16, redundant diagonal writes skipped)
    cudaFuncSetAttribute(stg_sym10_kernel, cudaFuncAttributeMaxDynamicSharedMemorySize, SMEM_BYTES);
    dim3 grid(TILES_PER_B, BB);
    stg_sym10_kernel<<<grid, 128, SMEM_BYTES>>>(out);
}